// round 17
// baseline (speedup 1.0000x reference)
#include <cuda_runtime.h>
#include <cuda_fp16.h>
#include <math.h>
#include <stdint.h>

// ConvEncoder: y = GELU(im2col(emb[x]) @ W^T + b).  M=32768, N=128, K=640.
// R17: R16 geometry (virtual padded token space, TOK=224, 147 CTAs = 99.3%
// one-wave fill, 3-slot W ring, single-pass fp16, tanh GELU) with 896
// threads / 28 warps (7 per SMSP) as 7m x 4n of 32x32 tiles: double the
// schedulable warps so LDSM-wait and MMA phases of different warps overlap.

#define CE_S    2048
#define CE_KTOT 640
#define THREADS 896
#define TOK     224
#define VROW    2052                 // 2048 + 4 pad rows per batch
#define N_CTA   147                  // ceil((16*2052 - 4) / 224)
#define ROW_B   272                  // fp16 row: 256B data + 16B pad (A and W)

// smem layout (bytes)
#define SA      0                    // 228 rows * 272 = 62016
#define SW_BASE 62016                // 3 slots x 34816 (128 rows * 272)
#define SW_SLOT 34816
#define SBIAS   166464
#define SIDX    166976               // 228 ints
#define SM_TOT  167936

// W pre-converted fp16: [kc(5)][o(128)][272B]
__device__ __align__(16) unsigned char g_Wcvt[5 * 128 * ROW_B];

// GELU, tanh form with HW MUFU tanh
__device__ __forceinline__ float gelu_fast(float x) {
    float t = x * fmaf(0.03567740814f, x * x, 0.79788456080f);
    float th;
    asm("tanh.approx.f32 %0, %1;" : "=f"(th) : "f"(t));
    float h = 0.5f * x;
    return fmaf(h, th, h);
}

__device__ __forceinline__ void mma_f16(float* c, const uint32_t* a, const uint32_t* b) {
    asm volatile(
        "mma.sync.aligned.m16n8k16.row.col.f32.f16.f16.f32 "
        "{%0,%1,%2,%3}, {%4,%5,%6,%7}, {%8,%9}, {%0,%1,%2,%3};"
        : "+f"(c[0]), "+f"(c[1]), "+f"(c[2]), "+f"(c[3])
        : "r"(a[0]), "r"(a[1]), "r"(a[2]), "r"(a[3]), "r"(b[0]), "r"(b[1]));
}

__device__ __forceinline__ void ldsm4(uint32_t* r, uint32_t addr) {
    asm volatile("ldmatrix.sync.aligned.m8n8.x4.shared.b16 {%0,%1,%2,%3}, [%4];"
                 : "=r"(r[0]), "=r"(r[1]), "=r"(r[2]), "=r"(r[3]) : "r"(addr));
}

__device__ __forceinline__ void cpasync16(uint32_t dst, const void* src) {
    asm volatile("cp.async.cg.shared.global [%0], [%1], 16;"
                 :: "r"(dst), "l"(src) : "memory");
}

// convert 8 f32 -> 8 fp16 packed as uint4 (16 bytes)
__device__ __forceinline__ uint4 cvt8_f16(float4 v0, float4 v1) {
    union { __half2 h[4]; uint4 u; } p;
    p.h[0] = __float22half2_rn(make_float2(v0.x, v0.y));
    p.h[1] = __float22half2_rn(make_float2(v0.z, v0.w));
    p.h[2] = __float22half2_rn(make_float2(v1.x, v1.y));
    p.h[3] = __float22half2_rn(make_float2(v1.z, v1.w));
    return p.u;
}

// ---- prep: W f32 -> fp16, chunked layout for direct cp.async ----
__global__ void __launch_bounds__(256)
prep_w_kernel(const float* __restrict__ W)
{
    int t = blockIdx.x * 256 + threadIdx.x;        // 5*128*16 = 10240 granules
    if (t >= 5 * 128 * 16) return;
    int gnl = t & 15;
    int o   = (t >> 4) & 127;
    int kc  = t >> 11;
    const float* src = W + (size_t)o * CE_KTOT + kc * 128 + gnl * 8;
    float4 v0 = *reinterpret_cast<const float4*>(src);
    float4 v1 = *reinterpret_cast<const float4*>(src + 4);
    *reinterpret_cast<uint4*>(g_Wcvt + ((size_t)kc * 128 + o) * ROW_B + gnl * 16)
        = cvt8_f16(v0, v1);
}

// stage one K=128 W chunk into a smem ring slot via cp.async
__device__ __forceinline__ void stage_w(uint32_t swdst, int kc, int tid) {
    const unsigned char* base = g_Wcvt + (size_t)kc * 128 * ROW_B;
    #pragma unroll
    for (int it = 0; it < 3; ++it) {
        int idx = tid + it * THREADS;              // 2048: 128 o x 16 granules
        if (idx < 2048) {
            int o = idx >> 4, gnl = idx & 15;
            cpasync16(swdst + o * ROW_B + gnl * 16,
                      base + (size_t)o * ROW_B + gnl * 16);
        }
    }
}

__global__ void __launch_bounds__(THREADS)
conv_encoder_hmma(const int* __restrict__ x,
                  const float* __restrict__ emb,
                  const float* __restrict__ bias,
                  float* __restrict__ out)
{
    extern __shared__ uint8_t smem[];
    uint32_t sb;
    asm("{ .reg .u64 t; cvta.to.shared.u64 t, %1; cvt.u32.u64 %0, t; }"
        : "=r"(sb) : "l"(smem));

    const int tid = threadIdx.x;
    const int wid = tid >> 5;
    const int lid = tid & 31;
    const int g   = lid >> 2;
    const int q   = lid & 3;
    const int wm  = wid >> 2;       // 0..6  (32-row band within 224)
    const int wn  = wid & 3;        // 0..3  (32-col band)
    const int o0  = blockIdx.x * TOK;   // base of this CTA in virtual space

    // prefetch W chunks 0 and 1 (overlaps the A gather)
    stage_w(sb + SW_BASE, 0, tid);
    asm volatile("cp.async.commit_group;" ::: "memory");
    stage_w(sb + SW_BASE + SW_SLOT, 1, tid);
    asm volatile("cp.async.commit_group;" ::: "memory");

    if (tid < 32) {
        reinterpret_cast<float4*>(smem + SBIAS)[tid] =
            reinterpret_cast<const float4*>(bias)[tid];
    }
    // token index cache: halo rows p=0..227 -> virtual v = o0+p,
    // b = v/2052, r = v%2052; valid token iff r in [2,2050) and b < 16.
    for (int p = tid; p < TOK + 4; p += THREADS) {
        int v = o0 + p;
        int b = v / VROW;
        int r = v - b * VROW;
        int tok = -1;
        if (b < 16 && r >= 2 && r < 2050)
            tok = x[b * CE_S + (r - 2)];
        reinterpret_cast<int*>(smem + SIDX)[p] = tok;
    }
    __syncthreads();

    // ---- stage halo'd A: rows p=0..227, fp16 (228*16 = 3648 granules) ----
    #pragma unroll
    for (int it = 0; it < 5; ++it) {
        int idx = tid + it * THREADS;
        if (idx < (TOK + 4) * 16) {
            int p = idx >> 4;
            int c = idx & 15;                      // 16B fp16 granule = 8 elems
            int tok = reinterpret_cast<const int*>(smem + SIDX)[p];
            float4 v0 = make_float4(0.f, 0.f, 0.f, 0.f);
            float4 v1 = v0;
            if (tok >= 0) {
                const float* e = emb + (size_t)tok * 128 + c * 8;
                v0 = *reinterpret_cast<const float4*>(e);
                v1 = *reinterpret_cast<const float4*>(e + 4);
            }
            *reinterpret_cast<uint4*>(smem + SA + p * ROW_B + c * 16) = cvt8_f16(v0, v1);
        }
    }

    float acc[2][4][4];
    #pragma unroll
    for (int i = 0; i < 2; ++i)
        #pragma unroll
        for (int j = 0; j < 4; ++j)
            #pragma unroll
            for (int r = 0; r < 4; ++r)
                acc[i][j][r] = 0.f;

    // per-lane ldmatrix offsets
    const uint32_t a_off = ((lid & 7) + ((lid >> 3) & 1) * 8) * ROW_B + (lid >> 4) * 16;
    // B (x4, j-paired): lanes 0-15 -> n-tile 2jp (k halves), 16-31 -> 2jp+1
    const uint32_t b_off = ((lid & 7) + (lid >> 4) * 8) * ROW_B + ((lid >> 3) & 1) * 16;

    // ---- 5 chunks of K=128 (window offsets), 3-slot ring, one sync/chunk ----
    #pragma unroll
    for (int s = 0; s < 5; ++s) {
        if (s < 4) {
            asm volatile("cp.async.wait_group 1;" ::: "memory");
        } else {
            asm volatile("cp.async.wait_group 0;" ::: "memory");
        }
        __syncthreads();
        if (s < 3) {
            stage_w(sb + SW_BASE + ((s + 2) % 3) * SW_SLOT, s + 2, tid);
            asm volatile("cp.async.commit_group;" ::: "memory");
        }

        const uint32_t swb = sb + SW_BASE + (s % 3) * SW_SLOT;
        const uint32_t aA  = sb + SA + (wm * 32 + s) * ROW_B + a_off;
        const uint32_t aB  = swb + wn * 32 * ROW_B + b_off;

        #pragma unroll
        for (int ks = 0; ks < 8; ++ks) {
            const uint32_t kb = ks * 32;
            uint32_t Aa[2][4], Bp[2][4];
            #pragma unroll
            for (int i = 0; i < 2; ++i)
                ldsm4(Aa[i], aA + i * (16 * ROW_B) + kb);
            #pragma unroll
            for (int jp = 0; jp < 2; ++jp)
                ldsm4(Bp[jp], aB + jp * (16 * ROW_B) + kb);
            #pragma unroll
            for (int i = 0; i < 2; ++i)
                #pragma unroll
                for (int j = 0; j < 4; ++j)
                    mma_f16(acc[i][j], Aa[i], &Bp[j >> 1][(j & 1) * 2]);
        }
    }

    // ---- epilogue: bias + fast GELU + predicated store (skip pad rows) ----
    const float* bs = reinterpret_cast<const float*>(smem + SBIAS);
    #pragma unroll
    for (int i = 0; i < 2; ++i) {
        #pragma unroll
        for (int half = 0; half < 2; ++half) {      // frag rows g and g+8
            int op = o0 + wm * 32 + i * 16 + half * 8 + g;   // virtual token
            int b  = op / VROW;
            int sq = op - b * VROW;
            if (b < 16 && sq < CE_S) {
                float* orow = out + ((size_t)(b * CE_S + sq)) * 128;
                #pragma unroll
                for (int j = 0; j < 4; ++j) {
                    int col = wn * 32 + j * 8 + q * 2;
                    float2 v;
                    v.x = gelu_fast(acc[i][j][2 * half]     + bs[col]);
                    v.y = gelu_fast(acc[i][j][2 * half + 1] + bs[col + 1]);
                    *reinterpret_cast<float2*>(orow + col) = v;
                }
            }
        }
    }
}

extern "C" void kernel_launch(void* const* d_in, const int* in_sizes, int n_in,
                              void* d_out, int out_size)
{
    const int*   x    = (const int*)  d_in[0];
    const float* emb  = (const float*)d_in[1];
    const float* W    = (const float*)d_in[2];
    const float* bias = (const float*)d_in[3];
    float*       out  = (float*)d_out;

    prep_w_kernel<<<40, 256>>>(W);

    cudaFuncSetAttribute(conv_encoder_hmma,
                         cudaFuncAttributeMaxDynamicSharedMemorySize, SM_TOT);
    conv_encoder_hmma<<<N_CTA, THREADS, SM_TOT>>>(x, emb, bias, out);
}